// round 6
// baseline (speedup 1.0000x reference)
#include <cuda_runtime.h>
#include <math.h>
#include <cstdint>

#define NN 1000
#define FF 64
#define BB 16
#define TT 12
#define KK 5
#define CC 10
#define EE 16000
#define SS (BB*TT)          /* 192 snapshots */
#define RR (SS*NN)          /* 192000 rows   */
#define KDIM 576            /* 9 terms * 64  */
#define GDIM 128            /* 2 gates * 64  */
#define PERB (TT*NN*FF)     /* 768000        */
#define NCHUNK 1500
#define CHSZ 512

// GEMM tiling
#define KC    48
#define NCH   12
#define SAS   52            /* smem row stride (floats), 16B aligned */
#define GSMEM (128*SAS*2*4) /* 53248 bytes */

// fused cheb smem: 4 planes (1000*8) + 2 inv tables (1000)
#define CSMEM ((4*8000 + 2000) * 4)   /* 136000 bytes */

// ---------------- scratch (static device globals; no runtime alloc) ----------
__device__ float g_TX[RR * KDIM];        // 442 MB: 9 Chebyshev term blocks
__device__ float g_HLN[RR * FF];         // 49 MB: layernormed hidden
__device__ float g_Wt[GDIM * KDIM];      // fused weights, transposed: [128 out][576 k]
__device__ int   g_deg_out[NN], g_deg_in[NN];
__device__ float g_inv_out[NN], g_inv_in[NN];
__device__ int   g_in_ptr[NN + 1], g_out_ptr[NN + 1];
__device__ unsigned short g_in_idx16[EE], g_out_idx16[EE];
__device__ int   g_cnt_in[NN], g_cnt_out[NN];
__device__ float g_part[NCHUNK * 160];

// ---------------- graph preprocessing ----------------------------------------
__global__ void k_zero() {
    int i = blockIdx.x * blockDim.x + threadIdx.x;
    if (i < NN) { g_deg_out[i] = 0; g_deg_in[i] = 0; g_cnt_in[i] = 0; g_cnt_out[i] = 0; }
}
__global__ void k_count(const int* __restrict__ ei) {
    int e = blockIdx.x * blockDim.x + threadIdx.x;
    if (e < EE) {
        atomicAdd(&g_deg_out[ei[e]], 1);
        atomicAdd(&g_deg_in[ei[EE + e]], 1);
    }
}
__global__ void k_scan() {
    if (threadIdx.x == 0 && blockIdx.x == 0) {
        int a = 0, b = 0;
        for (int n = 0; n < NN; n++) {
            g_in_ptr[n] = a;  g_out_ptr[n] = b;
            a += g_deg_in[n]; b += g_deg_out[n];
            g_inv_out[n] = 1.0f / (float)g_deg_out[n];
            g_inv_in[n]  = 1.0f / (float)g_deg_in[n];
        }
        g_in_ptr[NN] = a; g_out_ptr[NN] = b;
    }
}
__global__ void k_fill(const int* __restrict__ ei) {
    int e = blockIdx.x * blockDim.x + threadIdx.x;
    if (e < EE) {
        int s = ei[e], d = ei[EE + e];
        int p = atomicAdd(&g_cnt_in[d], 1);
        g_in_idx16[g_in_ptr[d] + p] = (unsigned short)s;
        int q = atomicAdd(&g_cnt_out[s], 1);
        g_out_idx16[g_out_ptr[s] + q] = (unsigned short)d;
    }
}

// ---------------- fused weight build (transposed: g_Wt[n][k]) -----------------
__global__ void k_wcat(const float* __restrict__ Wz, const float* __restrict__ Wh) {
    int i = blockIdx.x * blockDim.x + threadIdx.x;
    if (i >= KDIM * GDIM) return;
    int col  = i / KDIM, krow = i % KDIM;
    int term = krow / FF, ic = krow % FF;
    int gate = col / FF,  oc = col % FF;
    const float* W = (gate == 0) ? Wz : Wh;
    float v;
    if (term == 0)
        v = W[((0 * KK + 0) * 2 * FF + ic) * FF + oc] +
            W[((1 * KK + 0) * 2 * FF + ic) * FF + oc];
    else if (term <= 4)
        v = W[((0 * KK + term) * 2 * FF + ic) * FF + oc];
    else
        v = W[((1 * KK + (term - 4)) * 2 * FF + ic) * FF + oc];
    g_Wt[col * KDIM + krow] = v;
}

// ================= fused Chebyshev: all 4 steps, smem planes ==================
// CTA (512 thr) = (snapshot s, feature-group fg of 8). Planes [node][8f].
// o-planes hold inv_out[n]*value (pre-scaled); i-planes raw; sub read from gmem
// (same-thread RAW: each (node, feature) owned by one thread across all steps).
template<bool FIRST>
__device__ __forceinline__ void cheb_step(
    const float* __restrict__ So, const float* __restrict__ Si,
    float* __restrict__ Do, float* __restrict__ Di,
    float* __restrict__ txs, int sub, int to, int ti,
    int f, int nl, int c, const float* __restrict__ sio, const float* __restrict__ sii)
{
    for (int j = 0; j < 16; j++) {
        int n = nl + (j << 6);
        if (n >= NN) break;
        float accO = 0.f, accI = 0.f;
        int e = g_in_ptr[n], e0 = g_in_ptr[n + 1];
        for (; e + 4 <= e0; e += 4) {
            int i0 = g_in_idx16[e], i1 = g_in_idx16[e + 1];
            int i2 = g_in_idx16[e + 2], i3 = g_in_idx16[e + 3];
            float v0 = So[i0 * 8 + f], v1 = So[i1 * 8 + f];
            float v2 = So[i2 * 8 + f], v3 = So[i3 * 8 + f];
            if (FIRST) { v0 *= sio[i0]; v1 *= sio[i1]; v2 *= sio[i2]; v3 *= sio[i3]; }
            accO += (v0 + v1) + (v2 + v3);
        }
        for (; e < e0; e++) {
            int i0 = g_in_idx16[e];
            float v = So[i0 * 8 + f];
            if (FIRST) v *= sio[i0];
            accO += v;
        }
        e = g_out_ptr[n]; int e1 = g_out_ptr[n + 1];
        for (; e + 4 <= e1; e += 4) {
            int i0 = g_out_idx16[e], i1 = g_out_idx16[e + 1];
            int i2 = g_out_idx16[e + 2], i3 = g_out_idx16[e + 3];
            accI += (Si[i0 * 8 + f] + Si[i1 * 8 + f]) + (Si[i2 * 8 + f] + Si[i3 * 8 + f]);
        }
        for (; e < e1; e++) accI += Si[g_out_idx16[e] * 8 + f];
        accI *= sii[n];

        float rawO, rawI;
        if (FIRST) { rawO = accO; rawI = accI; }
        else {
            float t0 = txs[n * KDIM + sub * FF + c];
            rawO = fmaf(2.f, accO, -t0);
            rawI = fmaf(2.f, accI, -t0);
        }
        Do[n * 8 + f] = sio[n] * rawO;
        Di[n * 8 + f] = rawI;
        txs[n * KDIM + to * FF + c] = rawO;
        txs[n * KDIM + ti * FF + c] = rawI;
    }
    __syncthreads();
}

__global__ void __launch_bounds__(512) k_cheb_f(const float* __restrict__ x) {
    extern __shared__ float sp[];
    float* S0 = sp;
    float* S1 = sp + 8000;
    float* S2 = sp + 16000;
    float* S3 = sp + 24000;
    float* sio = sp + 32000;
    float* sii = sp + 33000;
    const int bx = blockIdx.x, s = bx >> 3, fg = bx & 7;
    const int tid = threadIdx.x, f = tid & 7, nl = tid >> 3;   // nl in 0..63
    const int c = fg * 8 + f;
    float* txs = g_TX + (size_t)s * NN * KDIM;

    for (int i = tid; i < NN; i += 512) { sio[i] = g_inv_out[i]; sii[i] = g_inv_in[i]; }
    for (int j = 0; j < 16; j++) {
        int n = nl + (j << 6);
        if (n >= NN) break;
        float v = x[((size_t)s * NN + n) * FF + c];
        S0[n * 8 + f] = v;
        txs[n * KDIM + c] = v;            // term 0
    }
    __syncthreads();

    cheb_step<true >(S0, S0, S1, S2, txs, -1, 1, 5, f, nl, c, sio, sii);
    cheb_step<false>(S1, S2, S3, S0, txs,  0, 2, 6, f, nl, c, sio, sii);
    cheb_step<false>(S3, S0, S1, S2, txs,  1, 3, 7, f, nl, c, sio, sii);
    cheb_step<false>(S1, S2, S3, S0, txs,  2, 4, 8, f, nl, c, sio, sii);
}

// ================= tf32 warp-MMA GEMM [RR,576]@[576,128] + fused epilogue =====
__device__ __forceinline__ uint32_t f2tf32(float f) {
    uint32_t r; asm("cvt.rna.tf32.f32 %0, %1;" : "=r"(r) : "f"(f)); return r;
}
__device__ __forceinline__ float4 cvt4(float4 v) {
    float4 r;
    r.x = __uint_as_float(f2tf32(v.x)); r.y = __uint_as_float(f2tf32(v.y));
    r.z = __uint_as_float(f2tf32(v.z)); r.w = __uint_as_float(f2tf32(v.w));
    return r;
}
#define MMA_TF32(c, a0, a1, a2, a3, b0, b1) \
    asm volatile("mma.sync.aligned.m16n8k8.row.col.f32.tf32.tf32.f32 " \
        "{%0,%1,%2,%3}, {%4,%5,%6,%7}, {%8,%9}, {%0,%1,%2,%3};" \
        : "+f"((c)[0]), "+f"((c)[1]), "+f"((c)[2]), "+f"((c)[3]) \
        : "r"(a0), "r"(a1), "r"(a2), "r"(a3), "r"(b0), "r"(b1))

__global__ void __launch_bounds__(256) k_gemm_mma(
    const float* __restrict__ bz, const float* __restrict__ bh,
    const float* __restrict__ lng, const float* __restrict__ lnb)
{
    extern __shared__ float sm[];
    float* sA = sm;                 // [128][52]
    float* sB = sm + 128 * SAS;     // [128][52]
    const int tid = threadIdx.x, wid = tid >> 5, lane = tid & 31;
    const int mg = wid >> 1, ng = wid & 1, g = lane >> 2, qc = lane & 3;
    const int row0 = blockIdx.x * 128;

    float acc[2][8][4];
#pragma unroll
    for (int a = 0; a < 2; a++)
#pragma unroll
        for (int j = 0; j < 8; j++)
#pragma unroll
            for (int d = 0; d < 4; d++) acc[a][j][d] = 0.f;

    const int rr = tid >> 1, hh = tid & 1;
    const float* Ag = g_TX + (size_t)(row0 + rr) * KDIM + hh * 24;
    const float* Bg = g_Wt + (size_t)rr * KDIM + hh * 24;
    float4 pa[6], pb[6];
#pragma unroll
    for (int i = 0; i < 6; i++) {
        pa[i] = *(const float4*)(Ag + i * 4);
        pb[i] = *(const float4*)(Bg + i * 4);
    }

#pragma unroll 1
    for (int ch = 0; ch < NCH; ch++) {
#pragma unroll
        for (int i = 0; i < 6; i++) {
            *(float4*)&sA[rr * SAS + hh * 24 + i * 4] = cvt4(pa[i]);
            *(float4*)&sB[rr * SAS + hh * 24 + i * 4] = cvt4(pb[i]);
        }
        __syncthreads();
        if (ch + 1 < NCH) {
#pragma unroll
            for (int i = 0; i < 6; i++) {
                pa[i] = *(const float4*)(Ag + (ch + 1) * KC + i * 4);
                pb[i] = *(const float4*)(Bg + (ch + 1) * KC + i * 4);
            }
        }
#pragma unroll
        for (int ks = 0; ks < 6; ks++) {
            const int k0 = ks * 8;
            uint32_t a[2][4];
#pragma unroll
            for (int mt = 0; mt < 2; mt++) {
                int r = mg * 32 + mt * 16 + g;
                a[mt][0] = __float_as_uint(sA[r * SAS + k0 + qc]);
                a[mt][1] = __float_as_uint(sA[(r + 8) * SAS + k0 + qc]);
                a[mt][2] = __float_as_uint(sA[r * SAS + k0 + qc + 4]);
                a[mt][3] = __float_as_uint(sA[(r + 8) * SAS + k0 + qc + 4]);
            }
#pragma unroll
            for (int j = 0; j < 8; j++) {
                int ntg = ((j >> 2) << 3) + (ng << 2) + (j & 3);
                int col = ntg * 8 + g;
                uint32_t b0 = __float_as_uint(sB[col * SAS + k0 + qc]);
                uint32_t b1 = __float_as_uint(sB[col * SAS + k0 + qc + 4]);
                MMA_TF32(acc[0][j], a[0][0], a[0][1], a[0][2], a[0][3], b0, b1);
                MMA_TF32(acc[1][j], a[1][0], a[1][1], a[1][2], a[1][3], b0, b1);
            }
        }
        __syncthreads();
    }

    // stage bias/LN params (sA region is dead)
    if (tid < 64) {
        sm[512 + tid] = bz[tid];
        sm[576 + tid] = bh[tid];
        sm[640 + tid] = lng[tid];
        sm[704 + tid] = lnb[tid];
    }
    __syncthreads();

    // gates + relu; per-row (sum, sumsq) partials to smem (rows split over ng)
    float hc[2][2][8];
#pragma unroll
    for (int mt = 0; mt < 2; mt++)
#pragma unroll
        for (int half = 0; half < 2; half++) {
            float sv = 0.f, sq = 0.f;
#pragma unroll
            for (int j = 0; j < 4; j++)
#pragma unroll
                for (int d = 0; d < 2; d++) {
                    int fz = ((ng << 2) + j) * 8 + qc * 2 + d;
                    float zl = acc[mt][j][half * 2 + d]     + sm[512 + fz];
                    float hl = acc[mt][j + 4][half * 2 + d] + sm[576 + fz];
                    float z  = 1.f / (1.f + __expf(-zl));
                    float v  = fmaxf((1.f - z) * tanhf(hl), 0.f);
                    hc[mt][half][j * 2 + d] = v;
                    sv += v; sq += v * v;
                }
            sv += __shfl_xor_sync(0xffffffffu, sv, 1);
            sq += __shfl_xor_sync(0xffffffffu, sq, 1);
            sv += __shfl_xor_sync(0xffffffffu, sv, 2);
            sq += __shfl_xor_sync(0xffffffffu, sq, 2);
            if (qc == 0) {
                int r = mg * 32 + mt * 16 + half * 8 + g;
                *(float2*)&sm[(r * 2 + ng) * 2] = make_float2(sv, sq);
            }
        }
    __syncthreads();

#pragma unroll
    for (int mt = 0; mt < 2; mt++)
#pragma unroll
        for (int half = 0; half < 2; half++) {
            int r = mg * 32 + mt * 16 + half * 8 + g;
            float2 p0 = *(float2*)&sm[(r * 2 + 0) * 2];
            float2 p1 = *(float2*)&sm[(r * 2 + 1) * 2];
            float mu = (p0.x + p1.x) * (1.f / 64.f);
            float var = (p0.y + p1.y) * (1.f / 64.f) - mu * mu;
            float rstd = rsqrtf(var + 1e-5f);
            float* op = g_HLN + (size_t)(row0 + r) * FF;
#pragma unroll
            for (int j = 0; j < 4; j++) {
                int f0 = ((ng << 2) + j) * 8 + qc * 2;
                float2 o;
                o.x = (hc[mt][half][j * 2]     - mu) * rstd * sm[640 + f0]     + sm[704 + f0];
                o.y = (hc[mt][half][j * 2 + 1] - mu) * rstd * sm[640 + f0 + 1] + sm[704 + f0 + 1];
                *(float2*)(op + f0) = o;
            }
        }
}

// ---------------- final linear: out[b,c] = <HLN[b,:], lin_w[c,:]> + lin_b -----
__global__ void k_lin1(const float* __restrict__ w) {
    int chunk = blockIdx.x;
    int tid = threadIdx.x;
    int b = tid / CC, c = tid % CC;
    const float4* hp = (const float4*)(g_HLN + b * PERB + chunk * CHSZ);
    const float4* wp = (const float4*)(w     + c * PERB + chunk * CHSZ);
    float acc = 0.f;
#pragma unroll 4
    for (int i = 0; i < CHSZ / 4; i++) {
        float4 hv = hp[i], wv = wp[i];
        acc += hv.x * wv.x + hv.y * wv.y + hv.z * wv.z + hv.w * wv.w;
    }
    g_part[chunk * 160 + tid] = acc;
}
__global__ void k_lin2(const float* __restrict__ lb, float* __restrict__ out) {
    int tid = threadIdx.x;
    if (tid < 160) {
        float acc = 0.f;
        for (int ch = 0; ch < NCHUNK; ch++) acc += g_part[ch * 160 + tid];
        int b = tid / CC, c = tid % CC;
        out[b * CC + c] = acc + lb[c];
    }
}

// ---------------- launch -------------------------------------------------------
extern "C" void kernel_launch(void* const* d_in, const int* in_sizes, int n_in,
                              void* d_out, int out_size) {
    const float* x    = (const float*)d_in[0];
    const int*   ei   = (const int*)  d_in[1];
    const float* Wz   = (const float*)d_in[2];
    const float* bz   = (const float*)d_in[3];
    // d_in[4], d_in[5] (W_r, b_r) are mathematically dead (h0 == 0)
    const float* Wh   = (const float*)d_in[6];
    const float* bh   = (const float*)d_in[7];
    const float* lng  = (const float*)d_in[8];
    const float* lnb  = (const float*)d_in[9];
    const float* lw   = (const float*)d_in[10];
    const float* lb   = (const float*)d_in[11];
    float* out = (float*)d_out;

    // idempotent, capture-safe, called every time (no static guards)
    cudaFuncSetAttribute(k_cheb_f, cudaFuncAttributeMaxDynamicSharedMemorySize, CSMEM);
    cudaFuncSetAttribute(k_gemm_mma, cudaFuncAttributeMaxDynamicSharedMemorySize, GSMEM);

    k_zero<<<4, 256>>>();
    k_count<<<(EE + 255) / 256, 256>>>(ei);
    k_scan<<<1, 32>>>();
    k_fill<<<(EE + 255) / 256, 256>>>(ei);
    k_wcat<<<(KDIM * GDIM + 255) / 256, 256>>>(Wz, Wh);

    k_cheb_f<<<SS * 8, 512, CSMEM>>>(x);

    k_gemm_mma<<<RR / 128, 256, GSMEM>>>(bz, bh, lng, lnb);

    k_lin1<<<NCHUNK, 160>>>(lw);
    k_lin2<<<1, 192>>>(lb, out);
}

// round 7
// speedup vs baseline: 1.4343x; 1.4343x over previous
#include <cuda_runtime.h>
#include <math.h>
#include <cstdint>

#define NN 1000
#define FF 64
#define BB 16
#define TT 12
#define KK 5
#define CC 10
#define EE 16000
#define SS (BB*TT)          /* 192 snapshots */
#define RR (SS*NN)          /* 192000 rows   */
#define KDIM 576            /* 9 terms * 64  */
#define GDIM 128            /* 2 gates * 64  */
#define PERB (TT*NN*FF)     /* 768000        */
#define NCHUNK 1500
#define CHSZ 512

// GEMM tiling
#define KC    48
#define NCH   12
#define SAS   52            /* smem row stride (floats), 16B aligned */
#define GSMEM (128*SAS*2*4) /* 53248 bytes */

// ---------------- scratch (static device globals; no runtime alloc) ----------
__device__ float g_TX[RR * KDIM];        // 442 MB: 9 Chebyshev term blocks
__device__ float g_HLN[RR * FF];         // 49 MB: layernormed hidden
__device__ float g_Wt[GDIM * KDIM];      // fused weights, transposed: [128 out][576 k]
__device__ int   g_deg_out[NN], g_deg_in[NN];
__device__ float g_inv_out[NN], g_inv_in[NN];
__device__ int   g_in_ptr[NN + 1], g_out_ptr[NN + 1];
__device__ int   g_in_idx[EE], g_out_idx[EE];
__device__ float g_in_w[EE];
__device__ int   g_cnt_in[NN], g_cnt_out[NN];
__device__ float g_part[NCHUNK * 160];

// ---------------- graph preprocessing ----------------------------------------
__global__ void k_zero() {
    int i = blockIdx.x * blockDim.x + threadIdx.x;
    if (i < NN) { g_deg_out[i] = 0; g_deg_in[i] = 0; g_cnt_in[i] = 0; g_cnt_out[i] = 0; }
}
__global__ void k_count(const int* __restrict__ ei) {
    int e = blockIdx.x * blockDim.x + threadIdx.x;
    if (e < EE) {
        atomicAdd(&g_deg_out[ei[e]], 1);
        atomicAdd(&g_deg_in[ei[EE + e]], 1);
    }
}
__global__ void k_scan() {
    if (threadIdx.x == 0 && blockIdx.x == 0) {
        int a = 0, b = 0;
        for (int n = 0; n < NN; n++) {
            g_in_ptr[n] = a;  g_out_ptr[n] = b;
            a += g_deg_in[n]; b += g_deg_out[n];
            g_inv_out[n] = 1.0f / (float)g_deg_out[n];
            g_inv_in[n]  = 1.0f / (float)g_deg_in[n];
        }
        g_in_ptr[NN] = a; g_out_ptr[NN] = b;
    }
}
__global__ void k_fill(const int* __restrict__ ei) {
    int e = blockIdx.x * blockDim.x + threadIdx.x;
    if (e < EE) {
        int s = ei[e], d = ei[EE + e];
        int p = atomicAdd(&g_cnt_in[d], 1);
        g_in_idx[g_in_ptr[d] + p] = s;
        g_in_w[g_in_ptr[d] + p]  = g_inv_out[s];
        int q = atomicAdd(&g_cnt_out[s], 1);
        g_out_idx[g_out_ptr[s] + q] = d;
    }
}

// ---------------- fused weight build (transposed: g_Wt[n][k]) -----------------
__global__ void k_wcat(const float* __restrict__ Wz, const float* __restrict__ Wh) {
    int i = blockIdx.x * blockDim.x + threadIdx.x;
    if (i >= KDIM * GDIM) return;
    int col  = i / KDIM, krow = i % KDIM;
    int term = krow / FF, ic = krow % FF;
    int gate = col / FF,  oc = col % FF;
    const float* W = (gate == 0) ? Wz : Wh;
    float v;
    if (term == 0)
        v = W[((0 * KK + 0) * 2 * FF + ic) * FF + oc] +
            W[((1 * KK + 0) * 2 * FF + ic) * FF + oc];
    else if (term <= 4)
        v = W[((0 * KK + term) * 2 * FF + ic) * FF + oc];
    else
        v = W[((1 * KK + (term - 4)) * 2 * FF + ic) * FF + oc];
    g_Wt[col * KDIM + krow] = v;
}

// ---------------- Tx0 copy -----------------------------------------------------
__global__ void k_copyx(const float* __restrict__ x) {
    int i = blockIdx.x * blockDim.x + threadIdx.x;
    if (i < RR * FF / 4) {
        int r = i / (FF / 4), f4 = i % (FF / 4);
        float4 v = ((const float4*)x)[i];
        *(float4*)&g_TX[r * KDIM + f4 * 4] = v;
    }
}

// ---------------- Chebyshev propagation step (proven R4 form) -----------------
__global__ void k_cheb(int so, int si, int dro, int dri, int sub) {
    int row = blockIdx.x * 4 + threadIdx.y;
    if (row >= RR) return;
    int f    = threadIdx.x;
    int node = row % NN;
    int sb   = (row - node) * KDIM;
    int rb   = row * KDIM;

    float acc_o = 0.f;
    int jb = g_in_ptr[node], je = g_in_ptr[node + 1];
    for (int j = jb; j < je; j++)
        acc_o += g_in_w[j] * g_TX[sb + g_in_idx[j] * KDIM + so * FF + f];

    float acc_i = 0.f;
    jb = g_out_ptr[node]; je = g_out_ptr[node + 1];
    for (int j = jb; j < je; j++)
        acc_i += g_TX[sb + g_out_idx[j] * KDIM + si * FF + f];
    acc_i *= g_inv_in[node];

    if (sub >= 0) {
        float t0 = g_TX[rb + sub * FF + f];
        acc_o = 2.f * acc_o - t0;
        acc_i = 2.f * acc_i - t0;
    }
    g_TX[rb + dro * FF + f] = acc_o;
    g_TX[rb + dri * FF + f] = acc_i;
}

// ================= tf32 warp-MMA GEMM [RR,576]@[576,128] + fused epilogue =====
__device__ __forceinline__ uint32_t f2tf32(float f) {
    uint32_t r; asm("cvt.rna.tf32.f32 %0, %1;" : "=r"(r) : "f"(f)); return r;
}
__device__ __forceinline__ float4 cvt4(float4 v) {
    float4 r;
    r.x = __uint_as_float(f2tf32(v.x)); r.y = __uint_as_float(f2tf32(v.y));
    r.z = __uint_as_float(f2tf32(v.z)); r.w = __uint_as_float(f2tf32(v.w));
    return r;
}
#define MMA_TF32(c, a0, a1, a2, a3, b0, b1) \
    asm volatile("mma.sync.aligned.m16n8k8.row.col.f32.tf32.tf32.f32 " \
        "{%0,%1,%2,%3}, {%4,%5,%6,%7}, {%8,%9}, {%0,%1,%2,%3};" \
        : "+f"((c)[0]), "+f"((c)[1]), "+f"((c)[2]), "+f"((c)[3]) \
        : "r"(a0), "r"(a1), "r"(a2), "r"(a3), "r"(b0), "r"(b1))

__global__ void __launch_bounds__(256) k_gemm_mma(
    const float* __restrict__ bz, const float* __restrict__ bh,
    const float* __restrict__ lng, const float* __restrict__ lnb)
{
    extern __shared__ float sm[];
    float* sA = sm;                 // [128][52]
    float* sB = sm + 128 * SAS;     // [128][52]
    const int tid = threadIdx.x, wid = tid >> 5, lane = tid & 31;
    const int mg = wid >> 1, ng = wid & 1, g = lane >> 2, qc = lane & 3;
    const int row0 = blockIdx.x * 128;

    float acc[2][8][4];
#pragma unroll
    for (int a = 0; a < 2; a++)
#pragma unroll
        for (int j = 0; j < 8; j++)
#pragma unroll
            for (int d = 0; d < 4; d++) acc[a][j][d] = 0.f;

    const int rr = tid >> 1, hh = tid & 1;
    const float* Ag = g_TX + (size_t)(row0 + rr) * KDIM + hh * 24;
    const float* Bg = g_Wt + (size_t)rr * KDIM + hh * 24;
    float4 pa[6], pb[6];
#pragma unroll
    for (int i = 0; i < 6; i++) {
        pa[i] = *(const float4*)(Ag + i * 4);
        pb[i] = *(const float4*)(Bg + i * 4);
    }

#pragma unroll 1
    for (int ch = 0; ch < NCH; ch++) {
#pragma unroll
        for (int i = 0; i < 6; i++) {
            *(float4*)&sA[rr * SAS + hh * 24 + i * 4] = cvt4(pa[i]);
            *(float4*)&sB[rr * SAS + hh * 24 + i * 4] = cvt4(pb[i]);
        }
        __syncthreads();
        if (ch + 1 < NCH) {
#pragma unroll
            for (int i = 0; i < 6; i++) {
                pa[i] = *(const float4*)(Ag + (ch + 1) * KC + i * 4);
                pb[i] = *(const float4*)(Bg + (ch + 1) * KC + i * 4);
            }
        }
#pragma unroll
        for (int ks = 0; ks < 6; ks++) {
            const int k0 = ks * 8;
            uint32_t a[2][4];
#pragma unroll
            for (int mt = 0; mt < 2; mt++) {
                int r = mg * 32 + mt * 16 + g;
                a[mt][0] = __float_as_uint(sA[r * SAS + k0 + qc]);
                a[mt][1] = __float_as_uint(sA[(r + 8) * SAS + k0 + qc]);
                a[mt][2] = __float_as_uint(sA[r * SAS + k0 + qc + 4]);
                a[mt][3] = __float_as_uint(sA[(r + 8) * SAS + k0 + qc + 4]);
            }
#pragma unroll
            for (int j = 0; j < 8; j++) {
                int ntg = ((j >> 2) << 3) + (ng << 2) + (j & 3);
                int col = ntg * 8 + g;
                uint32_t b0 = __float_as_uint(sB[col * SAS + k0 + qc]);
                uint32_t b1 = __float_as_uint(sB[col * SAS + k0 + qc + 4]);
                MMA_TF32(acc[0][j], a[0][0], a[0][1], a[0][2], a[0][3], b0, b1);
                MMA_TF32(acc[1][j], a[1][0], a[1][1], a[1][2], a[1][3], b0, b1);
            }
        }
        __syncthreads();
    }

    // stage bias/LN params (sA region is dead)
    if (tid < 64) {
        sm[512 + tid] = bz[tid];
        sm[576 + tid] = bh[tid];
        sm[640 + tid] = lng[tid];
        sm[704 + tid] = lnb[tid];
    }
    __syncthreads();

    // gates + relu; per-row (sum, sumsq) partials to smem (rows split over ng)
    float hc[2][2][8];
#pragma unroll
    for (int mt = 0; mt < 2; mt++)
#pragma unroll
        for (int half = 0; half < 2; half++) {
            float sv = 0.f, sq = 0.f;
#pragma unroll
            for (int j = 0; j < 4; j++)
#pragma unroll
                for (int d = 0; d < 2; d++) {
                    int fz = ((ng << 2) + j) * 8 + qc * 2 + d;
                    float zl = acc[mt][j][half * 2 + d]     + sm[512 + fz];
                    float hl = acc[mt][j + 4][half * 2 + d] + sm[576 + fz];
                    float z  = 1.f / (1.f + __expf(-zl));
                    float v  = fmaxf((1.f - z) * tanhf(hl), 0.f);
                    hc[mt][half][j * 2 + d] = v;
                    sv += v; sq += v * v;
                }
            sv += __shfl_xor_sync(0xffffffffu, sv, 1);
            sq += __shfl_xor_sync(0xffffffffu, sq, 1);
            sv += __shfl_xor_sync(0xffffffffu, sv, 2);
            sq += __shfl_xor_sync(0xffffffffu, sq, 2);
            if (qc == 0) {
                int r = mg * 32 + mt * 16 + half * 8 + g;
                *(float2*)&sm[(r * 2 + ng) * 2] = make_float2(sv, sq);
            }
        }
    __syncthreads();

#pragma unroll
    for (int mt = 0; mt < 2; mt++)
#pragma unroll
        for (int half = 0; half < 2; half++) {
            int r = mg * 32 + mt * 16 + half * 8 + g;
            float2 p0 = *(float2*)&sm[(r * 2 + 0) * 2];
            float2 p1 = *(float2*)&sm[(r * 2 + 1) * 2];
            float mu = (p0.x + p1.x) * (1.f / 64.f);
            float var = (p0.y + p1.y) * (1.f / 64.f) - mu * mu;
            float rstd = rsqrtf(var + 1e-5f);
            float* op = g_HLN + (size_t)(row0 + r) * FF;
#pragma unroll
            for (int j = 0; j < 4; j++) {
                int f0 = ((ng << 2) + j) * 8 + qc * 2;
                float2 o;
                o.x = (hc[mt][half][j * 2]     - mu) * rstd * sm[640 + f0]     + sm[704 + f0];
                o.y = (hc[mt][half][j * 2 + 1] - mu) * rstd * sm[640 + f0 + 1] + sm[704 + f0 + 1];
                *(float2*)(op + f0) = o;
            }
        }
}

// ---------------- final linear: out[b,c] = <HLN[b,:], lin_w[c,:]> + lin_b -----
__global__ void k_lin1(const float* __restrict__ w) {
    int chunk = blockIdx.x;
    int tid = threadIdx.x;
    int b = tid / CC, c = tid % CC;
    const float4* hp = (const float4*)(g_HLN + b * PERB + chunk * CHSZ);
    const float4* wp = (const float4*)(w     + c * PERB + chunk * CHSZ);
    float acc = 0.f;
#pragma unroll 4
    for (int i = 0; i < CHSZ / 4; i++) {
        float4 hv = hp[i], wv = wp[i];
        acc += hv.x * wv.x + hv.y * wv.y + hv.z * wv.z + hv.w * wv.w;
    }
    g_part[chunk * 160 + tid] = acc;
}
__global__ void k_lin2(const float* __restrict__ lb, float* __restrict__ out) {
    int tid = threadIdx.x;
    if (tid < 160) {
        float acc = 0.f;
        for (int ch = 0; ch < NCHUNK; ch++) acc += g_part[ch * 160 + tid];
        int b = tid / CC, c = tid % CC;
        out[b * CC + c] = acc + lb[c];
    }
}

// ---------------- launch -------------------------------------------------------
extern "C" void kernel_launch(void* const* d_in, const int* in_sizes, int n_in,
                              void* d_out, int out_size) {
    const float* x    = (const float*)d_in[0];
    const int*   ei   = (const int*)  d_in[1];
    const float* Wz   = (const float*)d_in[2];
    const float* bz   = (const float*)d_in[3];
    // d_in[4], d_in[5] (W_r, b_r) are mathematically dead (h0 == 0)
    const float* Wh   = (const float*)d_in[6];
    const float* bh   = (const float*)d_in[7];
    const float* lng  = (const float*)d_in[8];
    const float* lnb  = (const float*)d_in[9];
    const float* lw   = (const float*)d_in[10];
    const float* lb   = (const float*)d_in[11];
    float* out = (float*)d_out;

    // idempotent, capture-safe, no static guards
    cudaFuncSetAttribute(k_gemm_mma, cudaFuncAttributeMaxDynamicSharedMemorySize, GSMEM);

    k_zero<<<4, 256>>>();
    k_count<<<(EE + 255) / 256, 256>>>(ei);
    k_scan<<<1, 32>>>();
    k_fill<<<(EE + 255) / 256, 256>>>(ei);
    k_wcat<<<(KDIM * GDIM + 255) / 256, 256>>>(Wz, Wh);
    k_copyx<<<(RR * FF / 4 + 255) / 256, 256>>>(x);

    dim3 cb(64, 4);
    int cg = RR / 4;
    k_cheb<<<cg, cb>>>(0, 0, 1, 5, -1);   // Tx1o, Tx1i
    k_cheb<<<cg, cb>>>(1, 5, 2, 6, 0);    // Tx2o, Tx2i  (sub Tx0)
    k_cheb<<<cg, cb>>>(2, 6, 3, 7, 1);    // Tx3o, Tx3i  (sub Tx1o)
    k_cheb<<<cg, cb>>>(3, 7, 4, 8, 2);    // Tx4o, Tx4i  (sub Tx2o)

    k_gemm_mma<<<RR / 128, 256, GSMEM>>>(bz, bh, lng, lnb);

    k_lin1<<<NCHUNK, 160>>>(lw);
    k_lin2<<<1, 192>>>(lb, out);
}

// round 9
// speedup vs baseline: 1.7549x; 1.2235x over previous
#include <cuda_runtime.h>
#include <math.h>
#include <cstdint>

#define NN 1000
#define FF 64
#define BB 16
#define TT 12
#define KK 5
#define CC 10
#define EE 16000
#define SS (BB*TT)          /* 192 snapshots */
#define RR (SS*NN)          /* 192000 rows   */
#define KDIM 576            /* 9 terms * 64  */
#define GDIM 128            /* 2 gates * 64  */
#define PERB (TT*NN*FF)     /* 768000        */
#define NCHUNK 1500
#define CHSZ 512

// GEMM tiling
#define KC    48
#define NCH   12
#define SAS   52            /* smem row stride (floats), 16B aligned */
#define GSMEM (128*SAS*2*4) /* 53248 bytes */

// ---------------- scratch (static device globals; no runtime alloc) ----------
__device__ float g_TX[RR * KDIM];        // 442 MB: 9 Chebyshev term blocks
__device__ float g_HLN[RR * FF];         // 49 MB: layernormed hidden
__device__ float g_Wt[GDIM * KDIM];      // fused weights, transposed: [128 out][576 k]
__device__ int   g_deg_out[NN], g_deg_in[NN];
__device__ float g_inv_out[NN], g_inv_in[NN];
__device__ int   g_in_ptr[NN + 1], g_out_ptr[NN + 1];
__device__ int2  g_in_ew[EE];            // {src_idx, weight-bits} packed
__device__ int   g_out_idx[EE];
__device__ int   g_cnt_in[NN], g_cnt_out[NN];
__device__ float g_part[NCHUNK * 160];

// ---------------- graph preprocessing ----------------------------------------
__global__ void k_zero() {
    int i = blockIdx.x * blockDim.x + threadIdx.x;
    if (i < NN) { g_deg_out[i] = 0; g_deg_in[i] = 0; g_cnt_in[i] = 0; g_cnt_out[i] = 0; }
}
__global__ void k_count(const int* __restrict__ ei) {
    int e = blockIdx.x * blockDim.x + threadIdx.x;
    if (e < EE) {
        atomicAdd(&g_deg_out[ei[e]], 1);
        atomicAdd(&g_deg_in[ei[EE + e]], 1);
    }
}
__global__ void k_scan() {
    if (threadIdx.x == 0 && blockIdx.x == 0) {
        int a = 0, b = 0;
        for (int n = 0; n < NN; n++) {
            g_in_ptr[n] = a;  g_out_ptr[n] = b;
            a += g_deg_in[n]; b += g_deg_out[n];
            g_inv_out[n] = 1.0f / (float)g_deg_out[n];
            g_inv_in[n]  = 1.0f / (float)g_deg_in[n];
        }
        g_in_ptr[NN] = a; g_out_ptr[NN] = b;
    }
}
__global__ void k_fill(const int* __restrict__ ei) {
    int e = blockIdx.x * blockDim.x + threadIdx.x;
    if (e < EE) {
        int s = ei[e], d = ei[EE + e];
        int p = atomicAdd(&g_cnt_in[d], 1);
        g_in_ew[g_in_ptr[d] + p] = make_int2(s, __float_as_int(g_inv_out[s]));
        int q = atomicAdd(&g_cnt_out[s], 1);
        g_out_idx[g_out_ptr[s] + q] = d;
    }
}

// ---------------- fused weight build (transposed: g_Wt[n][k]) -----------------
__global__ void k_wcat(const float* __restrict__ Wz, const float* __restrict__ Wh) {
    int i = blockIdx.x * blockDim.x + threadIdx.x;
    if (i >= KDIM * GDIM) return;
    int col  = i / KDIM, krow = i % KDIM;
    int term = krow / FF, ic = krow % FF;
    int gate = col / FF,  oc = col % FF;
    const float* W = (gate == 0) ? Wz : Wh;
    float v;
    if (term == 0)
        v = W[((0 * KK + 0) * 2 * FF + ic) * FF + oc] +
            W[((1 * KK + 0) * 2 * FF + ic) * FF + oc];
    else if (term <= 4)
        v = W[((0 * KK + term) * 2 * FF + ic) * FF + oc];
    else
        v = W[((1 * KK + (term - 4)) * 2 * FF + ic) * FF + oc];
    g_Wt[col * KDIM + krow] = v;
}

// ---------------- Tx0 copy -----------------------------------------------------
__global__ void k_copyx(const float* __restrict__ x) {
    int i = blockIdx.x * blockDim.x + threadIdx.x;
    if (i < RR * FF / 4) {
        int r = i / (FF / 4), f4 = i % (FF / 4);
        float4 v = ((const float4*)x)[i];
        *(float4*)&g_TX[r * KDIM + f4 * 4] = v;
    }
}

// ---------------- Chebyshev propagation: warp per row, LDG.64 everywhere ------
__global__ void __launch_bounds__(256) k_cheb(int so, int si, int dro, int dri, int sub) {
    int row  = blockIdx.x * 8 + threadIdx.y;    // RR % 8 == 0
    int lane = threadIdx.x;                     // 0..31, feature pair
    int node = row % NN;
    size_t sb = (size_t)(row - node) * KDIM;
    size_t rb = (size_t)row * KDIM;

    const float* baseO = g_TX + sb + so * FF + 2 * lane;
    const float* baseI = g_TX + sb + si * FF + 2 * lane;

    float2 accO = make_float2(0.f, 0.f);
    int jb = g_in_ptr[node], je = g_in_ptr[node + 1];
    for (int j = jb; j < je; j++) {
        int2 ew = g_in_ew[j];                               // broadcast LDG.64
        float w = __int_as_float(ew.y);
        float2 v = *(const float2*)(baseO + (size_t)ew.x * KDIM);
        accO.x = fmaf(w, v.x, accO.x);
        accO.y = fmaf(w, v.y, accO.y);
    }

    float2 accI = make_float2(0.f, 0.f);
    jb = g_out_ptr[node]; je = g_out_ptr[node + 1];
    for (int j = jb; j < je; j++) {
        int ix = g_out_idx[j];                              // broadcast LDG.32
        float2 v = *(const float2*)(baseI + (size_t)ix * KDIM);
        accI.x += v.x;
        accI.y += v.y;
    }
    float wi = g_inv_in[node];
    accI.x *= wi; accI.y *= wi;

    if (sub >= 0) {
        float2 t0 = *(const float2*)(g_TX + rb + sub * FF + 2 * lane);
        accO.x = fmaf(2.f, accO.x, -t0.x);
        accO.y = fmaf(2.f, accO.y, -t0.y);
        accI.x = fmaf(2.f, accI.x, -t0.x);
        accI.y = fmaf(2.f, accI.y, -t0.y);
    }
    *(float2*)(g_TX + rb + dro * FF + 2 * lane) = accO;
    *(float2*)(g_TX + rb + dri * FF + 2 * lane) = accI;
}

// ================= tf32 warp-MMA GEMM [RR,576]@[576,128] + fused epilogue =====
__device__ __forceinline__ uint32_t f2tf32(float f) {
    uint32_t r; asm("cvt.rna.tf32.f32 %0, %1;" : "=r"(r) : "f"(f)); return r;
}
__device__ __forceinline__ float4 cvt4(float4 v) {
    float4 r;
    r.x = __uint_as_float(f2tf32(v.x)); r.y = __uint_as_float(f2tf32(v.y));
    r.z = __uint_as_float(f2tf32(v.z)); r.w = __uint_as_float(f2tf32(v.w));
    return r;
}
#define MMA_TF32(c, a0, a1, a2, a3, b0, b1) \
    asm volatile("mma.sync.aligned.m16n8k8.row.col.f32.tf32.tf32.f32 " \
        "{%0,%1,%2,%3}, {%4,%5,%6,%7}, {%8,%9}, {%0,%1,%2,%3};" \
        : "+f"((c)[0]), "+f"((c)[1]), "+f"((c)[2]), "+f"((c)[3]) \
        : "r"(a0), "r"(a1), "r"(a2), "r"(a3), "r"(b0), "r"(b1))

__global__ void __launch_bounds__(256) k_gemm_mma(
    const float* __restrict__ bz, const float* __restrict__ bh,
    const float* __restrict__ lng, const float* __restrict__ lnb)
{
    extern __shared__ float sm[];
    float* sA = sm;                 // [128][52]
    float* sB = sm + 128 * SAS;     // [128][52]
    const int tid = threadIdx.x, wid = tid >> 5, lane = tid & 31;
    const int mg = wid >> 1, ng = wid & 1, g = lane >> 2, qc = lane & 3;
    const int row0 = blockIdx.x * 128;

    float acc[2][8][4];
#pragma unroll
    for (int a = 0; a < 2; a++)
#pragma unroll
        for (int j = 0; j < 8; j++)
#pragma unroll
            for (int d = 0; d < 4; d++) acc[a][j][d] = 0.f;

    const int rr = tid >> 1, hh = tid & 1;
    const float* Ag = g_TX + (size_t)(row0 + rr) * KDIM + hh * 24;
    const float* Bg = g_Wt + (size_t)rr * KDIM + hh * 24;
    float4 pa[6], pb[6];
#pragma unroll
    for (int i = 0; i < 6; i++) {
        pa[i] = *(const float4*)(Ag + i * 4);
        pb[i] = *(const float4*)(Bg + i * 4);
    }

#pragma unroll 1
    for (int ch = 0; ch < NCH; ch++) {
#pragma unroll
        for (int i = 0; i < 6; i++) {
            *(float4*)&sA[rr * SAS + hh * 24 + i * 4] = cvt4(pa[i]);
            *(float4*)&sB[rr * SAS + hh * 24 + i * 4] = cvt4(pb[i]);
        }
        __syncthreads();
        if (ch + 1 < NCH) {
#pragma unroll
            for (int i = 0; i < 6; i++) {
                pa[i] = *(const float4*)(Ag + (ch + 1) * KC + i * 4);
                pb[i] = *(const float4*)(Bg + (ch + 1) * KC + i * 4);
            }
        }
#pragma unroll
        for (int ks = 0; ks < 6; ks++) {
            const int k0 = ks * 8;
            uint32_t a[2][4];
#pragma unroll
            for (int mt = 0; mt < 2; mt++) {
                int r = mg * 32 + mt * 16 + g;
                a[mt][0] = __float_as_uint(sA[r * SAS + k0 + qc]);
                a[mt][1] = __float_as_uint(sA[(r + 8) * SAS + k0 + qc]);
                a[mt][2] = __float_as_uint(sA[r * SAS + k0 + qc + 4]);
                a[mt][3] = __float_as_uint(sA[(r + 8) * SAS + k0 + qc + 4]);
            }
#pragma unroll
            for (int j = 0; j < 8; j++) {
                int ntg = ((j >> 2) << 3) + (ng << 2) + (j & 3);
                int col = ntg * 8 + g;
                uint32_t b0 = __float_as_uint(sB[col * SAS + k0 + qc]);
                uint32_t b1 = __float_as_uint(sB[col * SAS + k0 + qc + 4]);
                MMA_TF32(acc[0][j], a[0][0], a[0][1], a[0][2], a[0][3], b0, b1);
                MMA_TF32(acc[1][j], a[1][0], a[1][1], a[1][2], a[1][3], b0, b1);
            }
        }
        __syncthreads();
    }

    // stage bias/LN params (sA region is dead)
    if (tid < 64) {
        sm[512 + tid] = bz[tid];
        sm[576 + tid] = bh[tid];
        sm[640 + tid] = lng[tid];
        sm[704 + tid] = lnb[tid];
    }
    __syncthreads();

    // gates + relu; per-row (sum, sumsq) partials to smem (rows split over ng)
    float hc[2][2][8];
#pragma unroll
    for (int mt = 0; mt < 2; mt++)
#pragma unroll
        for (int half = 0; half < 2; half++) {
            float sv = 0.f, sq = 0.f;
#pragma unroll
            for (int j = 0; j < 4; j++)
#pragma unroll
                for (int d = 0; d < 2; d++) {
                    int fz = ((ng << 2) + j) * 8 + qc * 2 + d;
                    float zl = acc[mt][j][half * 2 + d]     + sm[512 + fz];
                    float hl = acc[mt][j + 4][half * 2 + d] + sm[576 + fz];
                    float z  = 1.f / (1.f + __expf(-zl));
                    float v  = fmaxf((1.f - z) * tanhf(hl), 0.f);
                    hc[mt][half][j * 2 + d] = v;
                    sv += v; sq += v * v;
                }
            sv += __shfl_xor_sync(0xffffffffu, sv, 1);
            sq += __shfl_xor_sync(0xffffffffu, sq, 1);
            sv += __shfl_xor_sync(0xffffffffu, sv, 2);
            sq += __shfl_xor_sync(0xffffffffu, sq, 2);
            if (qc == 0) {
                int r = mg * 32 + mt * 16 + half * 8 + g;
                *(float2*)&sm[(r * 2 + ng) * 2] = make_float2(sv, sq);
            }
        }
    __syncthreads();

#pragma unroll
    for (int mt = 0; mt < 2; mt++)
#pragma unroll
        for (int half = 0; half < 2; half++) {
            int r = mg * 32 + mt * 16 + half * 8 + g;
            float2 p0 = *(float2*)&sm[(r * 2 + 0) * 2];
            float2 p1 = *(float2*)&sm[(r * 2 + 1) * 2];
            float mu = (p0.x + p1.x) * (1.f / 64.f);
            float var = (p0.y + p1.y) * (1.f / 64.f) - mu * mu;
            float rstd = rsqrtf(var + 1e-5f);
            float* op = g_HLN + (size_t)(row0 + r) * FF;
#pragma unroll
            for (int j = 0; j < 4; j++) {
                int f0 = ((ng << 2) + j) * 8 + qc * 2;
                float2 o;
                o.x = (hc[mt][half][j * 2]     - mu) * rstd * sm[640 + f0]     + sm[704 + f0];
                o.y = (hc[mt][half][j * 2 + 1] - mu) * rstd * sm[640 + f0 + 1] + sm[704 + f0 + 1];
                *(float2*)(op + f0) = o;
            }
        }
}

// ---------------- final linear: out[b,c] = <HLN[b,:], lin_w[c,:]> + lin_b -----
__global__ void k_lin1(const float* __restrict__ w) {
    int chunk = blockIdx.x;
    int tid = threadIdx.x;
    int b = tid / CC, c = tid % CC;
    const float4* hp = (const float4*)(g_HLN + b * PERB + chunk * CHSZ);
    const float4* wp = (const float4*)(w     + c * PERB + chunk * CHSZ);
    float acc = 0.f;
#pragma unroll 4
    for (int i = 0; i < CHSZ / 4; i++) {
        float4 hv = hp[i], wv = wp[i];
        acc += hv.x * wv.x + hv.y * wv.y + hv.z * wv.z + hv.w * wv.w;
    }
    g_part[chunk * 160 + tid] = acc;
}
__global__ void k_lin2(const float* __restrict__ lb, float* __restrict__ out) {
    int tid = threadIdx.x;
    if (tid < 160) {
        float acc = 0.f;
        for (int ch = 0; ch < NCHUNK; ch++) acc += g_part[ch * 160 + tid];
        int b = tid / CC, c = tid % CC;
        out[b * CC + c] = acc + lb[c];
    }
}

// ---------------- launch -------------------------------------------------------
extern "C" void kernel_launch(void* const* d_in, const int* in_sizes, int n_in,
                              void* d_out, int out_size) {
    const float* x    = (const float*)d_in[0];
    const int*   ei   = (const int*)  d_in[1];
    const float* Wz   = (const float*)d_in[2];
    const float* bz   = (const float*)d_in[3];
    // d_in[4], d_in[5] (W_r, b_r) are mathematically dead (h0 == 0)
    const float* Wh   = (const float*)d_in[6];
    const float* bh   = (const float*)d_in[7];
    const float* lng  = (const float*)d_in[8];
    const float* lnb  = (const float*)d_in[9];
    const float* lw   = (const float*)d_in[10];
    const float* lb   = (const float*)d_in[11];
    float* out = (float*)d_out;

    // idempotent, capture-safe, no static guards
    cudaFuncSetAttribute(k_gemm_mma, cudaFuncAttributeMaxDynamicSharedMemorySize, GSMEM);

    k_zero<<<4, 256>>>();
    k_count<<<(EE + 255) / 256, 256>>>(ei);
    k_scan<<<1, 32>>>();
    k_fill<<<(EE + 255) / 256, 256>>>(ei);
    k_wcat<<<(KDIM * GDIM + 255) / 256, 256>>>(Wz, Wh);
    k_copyx<<<(RR * FF / 4 + 255) / 256, 256>>>(x);

    dim3 cb(32, 8);
    int cg = RR / 8;
    k_cheb<<<cg, cb>>>(0, 0, 1, 5, -1);   // Tx1o, Tx1i
    k_cheb<<<cg, cb>>>(1, 5, 2, 6, 0);    // Tx2o, Tx2i  (sub Tx0)
    k_cheb<<<cg, cb>>>(2, 6, 3, 7, 1);    // Tx3o, Tx3i  (sub Tx1o)
    k_cheb<<<cg, cb>>>(3, 7, 4, 8, 2);    // Tx4o, Tx4i  (sub Tx2o)

    k_gemm_mma<<<RR / 128, 256, GSMEM>>>(bz, bh, lng, lnb);

    k_lin1<<<NCHUNK, 160>>>(lw);
    k_lin2<<<1, 192>>>(lb, out);
}